// round 14
// baseline (speedup 1.0000x reference)
#include <cuda_runtime.h>
#include <math.h>

#define NB 64
#define HH 224
#define WW 224
#define C1 24
#define C2 48
#define H2 112
#define H4 56
#define EPSV 1e-5f
#define K2LEN 150528   /* C2*H4*H4 */
#define KCH 256
#define NCHUNK 588     /* 588*256 = 150528 */

// ---------------- scratch (static __device__, no allocation) ----------------
__device__ float g_x1[NB*C1*H2*H2];          // RAW pooled conv1 output (pre-BN)
__device__ float g_x2[NB*C2*H4*H4];          // RAW pooled conv2 output (pre-BN)
__device__ float g_U[16*C1*C2];              // Winograd-transformed conv2 weights
__device__ double g_s1[C1*64];               // 512B stride -> distinct LTS slices
__device__ double g_q1[C1*64];
__device__ double g_s2[C2*64];
__device__ double g_q2[C2*64];
__device__ float g_bn1s[C1], g_bn1b[C1];
__device__ float g_bn2s[C2], g_bn2b[C2];
__device__ float g_part[NCHUNK*NB*C2];
__device__ float g_feat[NB*C2];
__device__ float g_theta[NB*6];
__device__ unsigned g_cnt3;                  // last-block counter (feat_reduce only)

// ---------------- init: zero accumulators/counter + Winograd U --------------
__global__ void k_init(const float* __restrict__ wt) {
    int i = blockIdx.x*256 + threadIdx.x;
    if (i < C1*64) { g_s1[i] = 0.0; g_q1[i] = 0.0; }
    if (i < C2*64) { g_s2[i] = 0.0; g_q2[i] = 0.0; }
    if (i == 0) g_cnt3 = 0u;
    if (i < C2*C1) {
        int co = i / C1, ci = i - co*C1;
        const float* g = wt + i*9;
        float T[4][3];
#pragma unroll
        for (int c = 0; c < 3; c++) {
            float g0 = g[0*3+c], g1 = g[1*3+c], g2 = g[2*3+c];
            T[0][c] = g0;
            T[1][c] = 0.5f*(g0 + g1 + g2);
            T[2][c] = 0.5f*(g0 - g1 + g2);
            T[3][c] = g2;
        }
#pragma unroll
        for (int pr = 0; pr < 4; pr++) {
            float t0 = T[pr][0], t1 = T[pr][1], t2 = T[pr][2];
            g_U[((pr*4+0)*C1 + ci)*C2 + co] = t0;
            g_U[((pr*4+1)*C1 + ci)*C2 + co] = 0.5f*(t0 + t1 + t2);
            g_U[((pr*4+2)*C1 + ci)*C2 + co] = 0.5f*(t0 - t1 + t2);
            g_U[((pr*4+3)*C1 + ci)*C2 + co] = t2;
        }
    }
}

// ---------------- conv1: conv + stats + raw maxpool -------------------------
__global__ void __launch_bounds__(256) k_conv1(const float* __restrict__ x,
        const float* __restrict__ w, const float* __restrict__ bias) {
    __shared__ float ws[C1*9];
    __shared__ float wb[C1];
    __shared__ float bacc[C1*2];
    for (int i = threadIdx.x; i < C1*9; i += 256) ws[i] = w[i];
    if (threadIdx.x < C1) wb[threadIdx.x] = bias[threadIdx.x];
    if (threadIdx.x < C1*2) bacc[threadIdx.x] = 0.f;
    __syncthreads();

    int idx = blockIdx.x*256 + threadIdx.x;   // 64*112*112 exact
    int b   = idx / (H2*H2);
    int rem = idx - b*(H2*H2);
    int py  = rem / H2;
    int px  = rem - py*H2;
    const float* xb = x + b*HH*WW;

    float tap[4][4];
#pragma unroll
    for (int r = 0; r < 4; r++) {
        int gy = 2*py - 1 + r;
        bool vy = (unsigned)gy < HH;
#pragma unroll
        for (int cc = 0; cc < 4; cc++) {
            int gx = 2*px - 1 + cc;
            tap[r][cc] = (vy && (unsigned)gx < WW) ? xb[gy*WW + gx] : 0.f;
        }
    }
    int lane = threadIdx.x & 31;
    float* o1 = g_x1 + b*C1*H2*H2 + py*H2 + px;
#pragma unroll
    for (int c = 0; c < C1; c++) {
        float v00 = wb[c], v01 = wb[c], v10 = wb[c], v11 = wb[c];
#pragma unroll
        for (int r = 0; r < 3; r++)
#pragma unroll
        for (int k = 0; k < 3; k++) {
            float wv = ws[c*9 + r*3 + k];
            v00 = fmaf(wv, tap[r  ][k  ], v00);
            v01 = fmaf(wv, tap[r  ][k+1], v01);
            v10 = fmaf(wv, tap[r+1][k  ], v10);
            v11 = fmaf(wv, tap[r+1][k+1], v11);
        }
        o1[c*H2*H2] = fmaxf(fmaxf(v00, v01), fmaxf(v10, v11));
        float s = (v00+v01) + (v10+v11);
        float q = fmaf(v00,v00, fmaf(v01,v01, fmaf(v10,v10, v11*v11)));
        for (int o = 16; o > 0; o >>= 1) {
            s += __shfl_down_sync(0xffffffffu, s, o);
            q += __shfl_down_sync(0xffffffffu, q, o);
        }
        if (lane == 0) {
            atomicAdd(&bacc[c],      s);
            atomicAdd(&bacc[C1 + c], q);
        }
    }
    __syncthreads();
    if (threadIdx.x < C1)
        atomicAdd(&g_s1[threadIdx.x*64], (double)bacc[threadIdx.x]);
    else if (threadIdx.x < C1*2)
        atomicAdd(&g_q1[(threadIdx.x-C1)*64], (double)bacc[threadIdx.x]);
}

__global__ void k_fin1(const float* __restrict__ g, const float* __restrict__ b) {
    int c = threadIdx.x;
    if (c >= C1) return;
    double N = (double)NB*HH*WW;
    double m = g_s1[c*64] / N;
    double v = g_q1[c*64] / N - m*m;
    float sc = g[c] * rsqrtf((float)v + EPSV);
    g_bn1s[c] = sc;
    g_bn1b[c] = b[c] - (float)m * sc;
}

// ---------------- conv2 Winograd F(2x2,3x3), double-buffered V, 1 sync/p ----
// block: 16x16 output region = 8x8 Winograd tiles; thread: 6 co x 2 tiles.
// U read straight from global (L1-resident, warp-uniform broadcast).
__global__ void __launch_bounds__(256, 2) k_conv2w(const float* __restrict__ bias) {
    __shared__ __align__(16) float Is[C1*360];     // 24ci x 18 rows x stride20 = 34.6KB
    __shared__ __align__(16) float Vp[2*C1*64];    // double-buffered V = 12KB
    __shared__ float b1s_[C1], b1b_[C1];

    if (threadIdx.x < C1) {
        b1s_[threadIdx.x] = g_bn1s[threadIdx.x];
        b1b_[threadIdx.x] = g_bn1b[threadIdx.x];
    }
    __syncthreads();

    int blk = blockIdx.x;                 // 64 * 49
    int b   = blk / 49;
    int rem = blk - b*49;
    int by  = rem / 7;
    int bx  = rem - by*7;
    int oy0 = by*16, ox0 = bx*16;

    const float* x1b = g_x1 + b*C1*H2*H2;
    for (int i = threadIdx.x; i < C1*324; i += 256) {
        int ci = i / 324;
        int r2 = i - ci*324;
        int r  = r2 / 18;
        int c  = r2 - r*18;
        int gy = oy0 - 1 + r;
        int gx = ox0 - 1 + c;
        float v = ((unsigned)gy < H2 && (unsigned)gx < H2) ? x1b[(ci*H2 + gy)*H2 + gx] : 0.f;
        Is[ci*360 + r*20 + c] = fmaxf(fmaf(v, b1s_[ci], b1b_[ci]), 0.f);
    }

    int lane  = threadIdx.x & 31;
    int warp  = threadIdx.x >> 5;
    int warp6 = warp*6;
    int lane2 = lane*2;

    float y[6][2][4];
#pragma unroll
    for (int j = 0; j < 6; j++)
#pragma unroll
    for (int i = 0; i < 2; i++) {
        y[j][i][0] = 0.f; y[j][i][1] = 0.f; y[j][i][2] = 0.f; y[j][i][3] = 0.f;
    }

    const int   IA[4] = {0, 1, 1, 1};
    const int   IB[4] = {2, 2, 2, 3};
    const float SA[4] = {1.f, 1.f, -1.f, 1.f};
    const float SB[4] = {-1.f, 1.f, 1.f, -1.f};
    const int AT0[4] = {1, 1, 1, 0};
    const int AT1[4] = {0, 1, -1, -1};

    __syncthreads();                      // Is ready
    // prime: fill V(p=0) into buf 0
    {
        const int pr = 0, pc = 0;
        int ar0 = IA[pr]*20, ar1 = IB[pr]*20;
        int ac0 = IA[pc],    ac1 = IB[pc];
        float sr0 = SA[pr], sr1 = SB[pr];
        float c0 = SA[pc], c1 = SB[pc];
#pragma unroll
        for (int k = 0; k < 6; k++) {
            int v  = threadIdx.x + k*256;
            int ci = v >> 6;
            int t  = v & 63;
            int ty = t >> 3, tx = t & 7;
            const float* dP = Is + ci*360 + (2*ty)*20 + 2*tx;
            float d00 = dP[ar0 + ac0], d01 = dP[ar0 + ac1];
            float d10 = dP[ar1 + ac0], d11 = dP[ar1 + ac1];
            Vp[v] = sr0*(c0*d00 + c1*d01) + sr1*(c0*d10 + c1*d11);
        }
    }
    __syncthreads();

#pragma unroll
    for (int p = 0; p < 16; p++) {
        int buf = p & 1;
        // ---- prefetch V(p+1) into the other buffer (overlaps GEMM below) ----
        if (p < 15) {
            int pn = p + 1;
            int prn = pn >> 2, pcn = pn & 3;
            int ar0 = IA[prn]*20, ar1 = IB[prn]*20;
            int ac0 = IA[pcn],    ac1 = IB[pcn];
            float sr0 = SA[prn], sr1 = SB[prn];
            float c0 = SA[pcn], c1 = SB[pcn];
            float* Vd = Vp + (buf^1)*C1*64;
#pragma unroll
            for (int k = 0; k < 6; k++) {
                int v  = threadIdx.x + k*256;
                int ci = v >> 6;
                int t  = v & 63;
                int ty = t >> 3, tx = t & 7;
                const float* dP = Is + ci*360 + (2*ty)*20 + 2*tx;
                float d00 = dP[ar0 + ac0], d01 = dP[ar0 + ac1];
                float d10 = dP[ar1 + ac0], d11 = dP[ar1 + ac1];
                Vd[v] = sr0*(c0*d00 + c1*d01) + sr1*(c0*d10 + c1*d11);
            }
        }
        // ---- GEMM for p from Vp[buf]; U from global (broadcast LDG) --------
        const float* Vs = Vp + buf*C1*64;
        const float* Ug = g_U + p*C1*C2 + warp6;
        float m00=0.f, m01=0.f, m10=0.f, m11=0.f, m20=0.f, m21=0.f;
        float m30=0.f, m31=0.f, m40=0.f, m41=0.f, m50=0.f, m51=0.f;
#pragma unroll 6
        for (int ci = 0; ci < C1; ci++) {
            float2 vv = *(const float2*)&Vs[ci*64 + lane2];
            const float2* up = (const float2*)(Ug + ci*C2);
            float2 u0 = __ldg(up);
            float2 u1 = __ldg(up + 1);
            float2 u2 = __ldg(up + 2);
            m00 = fmaf(u0.x, vv.x, m00); m01 = fmaf(u0.x, vv.y, m01);
            m10 = fmaf(u0.y, vv.x, m10); m11 = fmaf(u0.y, vv.y, m11);
            m20 = fmaf(u1.x, vv.x, m20); m21 = fmaf(u1.x, vv.y, m21);
            m30 = fmaf(u1.y, vv.x, m30); m31 = fmaf(u1.y, vv.y, m31);
            m40 = fmaf(u2.x, vv.x, m40); m41 = fmaf(u2.x, vv.y, m41);
            m50 = fmaf(u2.y, vv.x, m50); m51 = fmaf(u2.y, vv.y, m51);
        }
        float mm[6][2] = {{m00,m01},{m10,m11},{m20,m21},{m30,m31},{m40,m41},{m50,m51}};
        int pr = p >> 2, pc = p & 3;
        int c00 = AT0[pr]*AT0[pc];
        int c01 = AT0[pr]*AT1[pc];
        int c10 = AT1[pr]*AT0[pc];
        int c11 = AT1[pr]*AT1[pc];
#pragma unroll
        for (int j = 0; j < 6; j++)
#pragma unroll
        for (int i = 0; i < 2; i++) {
            float v = mm[j][i];
            if (c00 ==  1) y[j][i][0] += v;
            if (c00 == -1) y[j][i][0] -= v;
            if (c01 ==  1) y[j][i][1] += v;
            if (c01 == -1) y[j][i][1] -= v;
            if (c10 ==  1) y[j][i][2] += v;
            if (c10 == -1) y[j][i][2] -= v;
            if (c11 ==  1) y[j][i][3] += v;
            if (c11 == -1) y[j][i][3] -= v;
        }
        __syncthreads();   // fill(p+1) visible; buf free for reuse at p+2
    }

    int ty = lane2 >> 3, tx = lane2 & 7;
    int pooy = by*8 + ty, poox = bx*8 + tx;
#pragma unroll
    for (int j = 0; j < 6; j++) {
        int co = warp6 + j;
        float bco = __ldg(&bias[co]);
        float s = 0.f, qq = 0.f;
        float pooled[2];
#pragma unroll
        for (int i = 0; i < 2; i++) {
            float v0 = y[j][i][0] + bco;
            float v1 = y[j][i][1] + bco;
            float v2 = y[j][i][2] + bco;
            float v3 = y[j][i][3] + bco;
            s += (v0+v1) + (v2+v3);
            qq = fmaf(v0,v0, fmaf(v1,v1, fmaf(v2,v2, fmaf(v3,v3, qq))));
            pooled[i] = fmaxf(fmaxf(v0, v1), fmaxf(v2, v3));
        }
        float* dst = g_x2 + ((b*C2 + co)*H4 + pooy)*H4 + poox;
        *(float2*)dst = make_float2(pooled[0], pooled[1]);
        for (int o = 16; o > 0; o >>= 1) {
            s  += __shfl_down_sync(0xffffffffu, s,  o);
            qq += __shfl_down_sync(0xffffffffu, qq, o);
        }
        if (lane == 0) {
            atomicAdd(&g_s2[co*64], (double)s);
            atomicAdd(&g_q2[co*64], (double)qq);
        }
    }
}

__global__ void k_fin2(const float* __restrict__ g, const float* __restrict__ b) {
    int c = threadIdx.x;
    if (c >= C2) return;
    double N = (double)NB*H2*H2;
    double m = g_s2[c*64] / N;
    double v = g_q2[c*64] / N - m*m;
    float sc = g[c] * rsqrtf((float)v + EPSV);
    g_bn2s[c] = sc;
    g_bn2b[c] = b[c] - (float)m * sc;
}

// ---------------- feat GEMM split-K (R9 layout — measured 50.7us) -----------
__global__ void __launch_bounds__(256) k_feat_part(const float* __restrict__ fw) {
    __shared__ float xs[NB*33];
    __shared__ float wsm[C2*33];
    int k0  = blockIdx.x * KCH;
    int tid = threadIdx.x;
    int bi  = tid & 15;
    int oi  = tid >> 4;
    int kl  = tid & 31;
    int rr  = tid >> 5;
    float acc[4][3];
#pragma unroll
    for (int i = 0; i < 4; i++)
#pragma unroll
    for (int j = 0; j < 3; j++) acc[i][j] = 0.f;

#pragma unroll 1
    for (int kk = 0; kk < KCH; kk += 32) {
        __syncthreads();
        int kidx = k0 + kk + kl;
        int ch   = kidx / (H4*H4);
        float sc = g_bn2s[ch], sh = g_bn2b[ch];
#pragma unroll
        for (int r = 0; r < 8; r++) {
            int bb = r*8 + rr;
            float raw = g_x2[bb*K2LEN + kidx];
            xs[bb*33 + kl] = fmaxf(fmaf(raw, sc, sh), 0.f);
        }
#pragma unroll
        for (int r = 0; r < 6; r++) {
            int oo = r*8 + rr;
            wsm[oo*33 + kl] = fw[(size_t)oo*K2LEN + kidx];
        }
        __syncthreads();
#pragma unroll
        for (int k = 0; k < 32; k++) {
            float xv[4], wv[3];
#pragma unroll
            for (int i = 0; i < 4; i++) xv[i] = xs[(bi*4 + i)*33 + k];
#pragma unroll
            for (int j = 0; j < 3; j++) wv[j] = wsm[(oi*3 + j)*33 + k];
#pragma unroll
            for (int i = 0; i < 4; i++)
#pragma unroll
            for (int j = 0; j < 3; j++)
                acc[i][j] = fmaf(xv[i], wv[j], acc[i][j]);
        }
    }
#pragma unroll
    for (int i = 0; i < 4; i++)
#pragma unroll
    for (int j = 0; j < 3; j++)
        g_part[(size_t)blockIdx.x*NB*C2 + (bi*4 + i)*C2 + (oi*3 + j)] = acc[i][j];
}

// ---------------- feat reduce + (last block, 12-block grid) MLP head --------
__global__ void k_feat_reduce(const float* __restrict__ fb,
                              const float* __restrict__ l1w, const float* __restrict__ l1b,
                              const float* __restrict__ l2w, const float* __restrict__ l2b,
                              float* __restrict__ out) {
    __shared__ bool isLast;
    int i = blockIdx.x*256 + threadIdx.x;
    if (i < NB*C2) {
        float s = 0.f;
#pragma unroll 4
        for (int n = 0; n < NCHUNK; n++) s += g_part[n*NB*C2 + i];
        g_feat[i] = s + fb[i % C2];
    }
    __syncthreads();
    if (threadIdx.x == 0) {
        __threadfence();
        isLast = (atomicAdd(&g_cnt3, 1u) == gridDim.x - 1u);
    }
    __syncthreads();
    if (isLast && threadIdx.x < NB) {
        int b = threadIdx.x;
        float f[48];
#pragma unroll
        for (int k = 0; k < 48; k++) f[k] = __ldcg(&g_feat[b*48 + k]);
        float h[24];
#pragma unroll 1
        for (int j = 0; j < 24; j++) {
            float s = l1b[j];
            for (int k = 0; k < 48; k++)
                s = fmaf(l1w[j*48 + k], f[k], s);
            h[j] = fmaxf(s, 0.f);
        }
        float t[4];
#pragma unroll
        for (int ii = 0; ii < 4; ii++) {
            float s = l2b[ii];
#pragma unroll
            for (int j = 0; j < 24; j++)
                s = fmaf(l2w[ii*24 + j], h[j], s);
            t[ii] = s;
        }
        float tx = t[0], tyv = t[1], sc = t[2], an = t[3];
        float cs = cosf(an), sn = sinf(an);
        g_theta[b*6 + 0] =  sc*cs;
        g_theta[b*6 + 1] = -sc*sn;
        g_theta[b*6 + 2] =  tx;
        g_theta[b*6 + 3] =  sc*sn;
        g_theta[b*6 + 4] =  sc*cs;
        g_theta[b*6 + 5] =  tyv;
        out[NB*HH*WW +         b] = tx;
        out[NB*HH*WW +  64 +   b] = tyv;
        out[NB*HH*WW + 128 +   b] = sc;
        out[NB*HH*WW + 192 +   b] = an;
    }
}

// ---------------- affine grid + bilinear sample -----------------------------
__device__ __forceinline__ float tapf(const float* __restrict__ xb,
                                      float xf, float yf, float wgt) {
    bool valid = (xf >= 0.f) & (xf < (float)WW) & (yf >= 0.f) & (yf < (float)HH);
    int xi = (int)fminf(fmaxf(xf, 0.f), (float)(WW-1));
    int yi = (int)fminf(fmaxf(yf, 0.f), (float)(HH-1));
    float v = __ldg(&xb[yi*WW + xi]);
    return valid ? v*wgt : 0.f;
}

__global__ void k_sample(const float* __restrict__ x, float* __restrict__ out) {
    int idx = blockIdx.x*256 + threadIdx.x;      // 64*224*224 exact
    int b   = idx / (HH*WW);
    int rem = idx - b*(HH*WW);
    int r   = rem / WW;
    int c   = rem - r*WW;
    float xsn = (2.f*c + 1.f)/(float)WW - 1.f;
    float ysn = (2.f*r + 1.f)/(float)HH - 1.f;
    const float* th = g_theta + b*6;
    float gx = th[0]*xsn + th[1]*ysn + th[2];
    float gy = th[3]*xsn + th[4]*ysn + th[5];
    float ix = ((gx + 1.f)*(float)WW - 1.f)*0.5f;
    float iy = ((gy + 1.f)*(float)HH - 1.f)*0.5f;
    float x0 = floorf(ix), y0 = floorf(iy);
    float x1 = x0 + 1.f,   y1 = y0 + 1.f;
    float wx1 = ix - x0, wx0 = 1.f - wx1;
    float wy1 = iy - y0, wy0 = 1.f - wy1;
    const float* xb = x + b*HH*WW;
    float o = tapf(xb, x0, y0, wx0*wy0)
            + tapf(xb, x1, y0, wx1*wy0)
            + tapf(xb, x0, y1, wx0*wy1)
            + tapf(xb, x1, y1, wx1*wy1);
    out[idx] = o;
}

// ---------------- launch ----------------------------------------------------
extern "C" void kernel_launch(void* const* d_in, const int* in_sizes, int n_in,
                              void* d_out, int out_size) {
    (void)in_sizes; (void)n_in; (void)out_size;
    const float* x    = (const float*)d_in[0];
    const float* c1w  = (const float*)d_in[1];
    const float* c1b  = (const float*)d_in[2];
    const float* bn1g = (const float*)d_in[3];
    const float* bn1b = (const float*)d_in[4];
    const float* c2w  = (const float*)d_in[5];
    const float* c2b  = (const float*)d_in[6];
    const float* bn2g = (const float*)d_in[7];
    const float* bn2b = (const float*)d_in[8];
    const float* fw   = (const float*)d_in[9];
    const float* fb   = (const float*)d_in[10];
    const float* l1w  = (const float*)d_in[11];
    const float* l1b  = (const float*)d_in[12];
    const float* l2w  = (const float*)d_in[13];
    const float* l2b  = (const float*)d_in[14];
    float* out = (float*)d_out;

    k_init<<<12, 256>>>(c2w);
    k_conv1<<<3136, 256>>>(x, c1w, c1b);
    k_fin1<<<1, 32>>>(bn1g, bn1b);
    k_conv2w<<<NB*49, 256>>>(c2b);
    k_fin2<<<1, 64>>>(bn2g, bn2b);
    k_feat_part<<<NCHUNK, 256>>>(fw);
    k_feat_reduce<<<12, 256>>>(fb, l1w, l1b, l2w, l2b, out);
    k_sample<<<(NB*HH*WW)/256, 256>>>(x, out);
}

// round 15
// speedup vs baseline: 1.3078x; 1.3078x over previous
#include <cuda_runtime.h>
#include <math.h>

#define NB 64
#define HH 224
#define WW 224
#define C1 24
#define C2 48
#define H2 112
#define H4 56
#define EPSV 1e-5f
#define K2LEN 150528   /* C2*H4*H4 */
#define KCH 256
#define NCHUNK 588     /* 588*256 = 150528 */

#define INV_N1 (1.0/((double)NB*HH*WW))
#define INV_N2 (1.0/((double)NB*H2*H2))

// ---------------- scratch (static __device__, no allocation) ----------------
__device__ float g_x1[NB*C1*H2*H2];          // RAW pooled conv1 output (pre-BN)
__device__ float g_x2[NB*C2*H4*H4];          // RAW pooled conv2 output (pre-BN)
__device__ float g_U[16*C1*C2];              // Winograd-transformed conv2 weights
__device__ double g_s1[C1*64];               // 512B stride -> distinct LTS slices
__device__ double g_q1[C1*64];
__device__ double g_s2[C2*64];
__device__ double g_q2[C2*64];
__device__ float g_part[NCHUNK*NB*C2];
__device__ float g_feat[NB*C2];
__device__ float g_theta[NB*6];
__device__ unsigned g_cnt3;                  // last-block counter (feat_reduce only)

// ---------------- init: zero accumulators/counter + Winograd U --------------
__global__ void k_init(const float* __restrict__ wt) {
    int i = blockIdx.x*256 + threadIdx.x;
    if (i < C1*64) { g_s1[i] = 0.0; g_q1[i] = 0.0; }
    if (i < C2*64) { g_s2[i] = 0.0; g_q2[i] = 0.0; }
    if (i == 0) g_cnt3 = 0u;
    if (i < C2*C1) {
        int co = i / C1, ci = i - co*C1;
        const float* g = wt + i*9;
        float T[4][3];
#pragma unroll
        for (int c = 0; c < 3; c++) {
            float g0 = g[0*3+c], g1 = g[1*3+c], g2 = g[2*3+c];
            T[0][c] = g0;
            T[1][c] = 0.5f*(g0 + g1 + g2);
            T[2][c] = 0.5f*(g0 - g1 + g2);
            T[3][c] = g2;
        }
#pragma unroll
        for (int pr = 0; pr < 4; pr++) {
            float t0 = T[pr][0], t1 = T[pr][1], t2 = T[pr][2];
            g_U[((pr*4+0)*C1 + ci)*C2 + co] = t0;
            g_U[((pr*4+1)*C1 + ci)*C2 + co] = 0.5f*(t0 + t1 + t2);
            g_U[((pr*4+2)*C1 + ci)*C2 + co] = 0.5f*(t0 - t1 + t2);
            g_U[((pr*4+3)*C1 + ci)*C2 + co] = t2;
        }
    }
}

// ---------------- conv1: conv + stats + raw maxpool -------------------------
__global__ void __launch_bounds__(256) k_conv1(const float* __restrict__ x,
        const float* __restrict__ w, const float* __restrict__ bias) {
    __shared__ float ws[C1*9];
    __shared__ float wb[C1];
    __shared__ float bacc[C1*2];
    for (int i = threadIdx.x; i < C1*9; i += 256) ws[i] = w[i];
    if (threadIdx.x < C1) wb[threadIdx.x] = bias[threadIdx.x];
    if (threadIdx.x < C1*2) bacc[threadIdx.x] = 0.f;
    __syncthreads();

    int idx = blockIdx.x*256 + threadIdx.x;   // 64*112*112 exact
    int b   = idx / (H2*H2);
    int rem = idx - b*(H2*H2);
    int py  = rem / H2;
    int px  = rem - py*H2;
    const float* xb = x + b*HH*WW;

    float tap[4][4];
#pragma unroll
    for (int r = 0; r < 4; r++) {
        int gy = 2*py - 1 + r;
        bool vy = (unsigned)gy < HH;
#pragma unroll
        for (int cc = 0; cc < 4; cc++) {
            int gx = 2*px - 1 + cc;
            tap[r][cc] = (vy && (unsigned)gx < WW) ? xb[gy*WW + gx] : 0.f;
        }
    }
    int lane = threadIdx.x & 31;
    float* o1 = g_x1 + b*C1*H2*H2 + py*H2 + px;
#pragma unroll
    for (int c = 0; c < C1; c++) {
        float v00 = wb[c], v01 = wb[c], v10 = wb[c], v11 = wb[c];
#pragma unroll
        for (int r = 0; r < 3; r++)
#pragma unroll
        for (int k = 0; k < 3; k++) {
            float wv = ws[c*9 + r*3 + k];
            v00 = fmaf(wv, tap[r  ][k  ], v00);
            v01 = fmaf(wv, tap[r  ][k+1], v01);
            v10 = fmaf(wv, tap[r+1][k  ], v10);
            v11 = fmaf(wv, tap[r+1][k+1], v11);
        }
        o1[c*H2*H2] = fmaxf(fmaxf(v00, v01), fmaxf(v10, v11));
        float s = (v00+v01) + (v10+v11);
        float q = fmaf(v00,v00, fmaf(v01,v01, fmaf(v10,v10, v11*v11)));
        for (int o = 16; o > 0; o >>= 1) {
            s += __shfl_down_sync(0xffffffffu, s, o);
            q += __shfl_down_sync(0xffffffffu, q, o);
        }
        if (lane == 0) {
            atomicAdd(&bacc[c],      s);
            atomicAdd(&bacc[C1 + c], q);
        }
    }
    __syncthreads();
    if (threadIdx.x < C1)
        atomicAdd(&g_s1[threadIdx.x*64], (double)bacc[threadIdx.x]);
    else if (threadIdx.x < C1*2)
        atomicAdd(&g_q1[(threadIdx.x-C1)*64], (double)bacc[threadIdx.x]);
}

// ---------------- conv2 Winograd F(2x2,3x3) (R13-measured version) ----------
// bn1 finalize folded in: every block recomputes scale/shift from the complete
// g_s1/g_q1 (kernel-boundary ordering; deterministic; smem-only).
__global__ void __launch_bounds__(256, 2) k_conv2w(const float* __restrict__ bias,
        const float* __restrict__ bn1g, const float* __restrict__ bn1b) {
    __shared__ __align__(16) float Is[C1*360];   // 24ci x 18 rows x stride20
    __shared__ __align__(16) float Vp[C1*64];    // per-p V
    __shared__ __align__(16) float Us[C1*C2];    // per-p U
    __shared__ float b1s_[C1], b1b_[C1];

    if (threadIdx.x < C1) {
        int c = threadIdx.x;
        double m = g_s1[c*64] * INV_N1;
        double v = g_q1[c*64] * INV_N1 - m*m;
        float sc = bn1g[c] * rsqrtf((float)v + EPSV);
        b1s_[c] = sc;
        b1b_[c] = bn1b[c] - (float)m * sc;
    }
    __syncthreads();

    int blk = blockIdx.x;                 // 64 * 49
    int b   = blk / 49;
    int rem = blk - b*49;
    int by  = rem / 7;
    int bx  = rem - by*7;
    int oy0 = by*16, ox0 = bx*16;

    const float* x1b = g_x1 + b*C1*H2*H2;
    for (int i = threadIdx.x; i < C1*324; i += 256) {
        int ci = i / 324;
        int r2 = i - ci*324;
        int r  = r2 / 18;
        int c  = r2 - r*18;
        int gy = oy0 - 1 + r;
        int gx = ox0 - 1 + c;
        float v = ((unsigned)gy < H2 && (unsigned)gx < H2) ? x1b[(ci*H2 + gy)*H2 + gx] : 0.f;
        Is[ci*360 + r*20 + c] = fmaxf(fmaf(v, b1s_[ci], b1b_[ci]), 0.f);
    }

    int lane  = threadIdx.x & 31;
    int warp  = threadIdx.x >> 5;
    int warp6 = warp*6;
    int lane2 = lane*2;

    float y[6][2][4];
#pragma unroll
    for (int j = 0; j < 6; j++)
#pragma unroll
    for (int i = 0; i < 2; i++) {
        y[j][i][0] = 0.f; y[j][i][1] = 0.f; y[j][i][2] = 0.f; y[j][i][3] = 0.f;
    }

    const int   IA[4] = {0, 1, 1, 1};
    const int   IB[4] = {2, 2, 2, 3};
    const float SA[4] = {1.f, 1.f, -1.f, 1.f};
    const float SB[4] = {-1.f, 1.f, 1.f, -1.f};
    const int AT0[4] = {1, 1, 1, 0};
    const int AT1[4] = {0, 1, -1, -1};

#pragma unroll
    for (int pr = 0; pr < 4; pr++) {
#pragma unroll
        for (int pc = 0; pc < 4; pc++) {
            int p = pr*4 + pc;
            __syncthreads();
            {
                int ar0 = IA[pr]*20, ar1 = IB[pr]*20;
                int ac0 = IA[pc],    ac1 = IB[pc];
                float sr0 = SA[pr], sr1 = SB[pr];
                float sc0 = SA[pc], sc1 = SB[pc];
#pragma unroll
                for (int k = 0; k < 6; k++) {
                    int v  = threadIdx.x + k*256;
                    int ci = v >> 6;
                    int t  = v & 63;
                    int ty = t >> 3, tx = t & 7;
                    const float* dP = Is + ci*360 + (2*ty)*20 + 2*tx;
                    float d00 = dP[ar0 + ac0], d01 = dP[ar0 + ac1];
                    float d10 = dP[ar1 + ac0], d11 = dP[ar1 + ac1];
                    Vp[v] = sr0*(sc0*d00 + sc1*d01) + sr1*(sc0*d10 + sc1*d11);
                }
                const float* Ug = g_U + p*C1*C2;
#pragma unroll
                for (int k = 0; k < 5; k++) {
                    int v = threadIdx.x + k*256;
                    if (v < C1*C2) Us[v] = Ug[v];
                }
            }
            __syncthreads();
            float m00=0.f, m01=0.f, m10=0.f, m11=0.f, m20=0.f, m21=0.f;
            float m30=0.f, m31=0.f, m40=0.f, m41=0.f, m50=0.f, m51=0.f;
#pragma unroll 6
            for (int ci = 0; ci < C1; ci++) {
                float2 vv = *(const float2*)&Vp[ci*64 + lane2];
                const float* up = &Us[ci*C2 + warp6];
                float2 u0 = *(const float2*)(up);
                float2 u1 = *(const float2*)(up + 2);
                float2 u2 = *(const float2*)(up + 4);
                m00 = fmaf(u0.x, vv.x, m00); m01 = fmaf(u0.x, vv.y, m01);
                m10 = fmaf(u0.y, vv.x, m10); m11 = fmaf(u0.y, vv.y, m11);
                m20 = fmaf(u1.x, vv.x, m20); m21 = fmaf(u1.x, vv.y, m21);
                m30 = fmaf(u1.y, vv.x, m30); m31 = fmaf(u1.y, vv.y, m31);
                m40 = fmaf(u2.x, vv.x, m40); m41 = fmaf(u2.x, vv.y, m41);
                m50 = fmaf(u2.y, vv.x, m50); m51 = fmaf(u2.y, vv.y, m51);
            }
            float mm[6][2] = {{m00,m01},{m10,m11},{m20,m21},{m30,m31},{m40,m41},{m50,m51}};
            int c00 = AT0[pr]*AT0[pc];
            int c01 = AT0[pr]*AT1[pc];
            int c10 = AT1[pr]*AT0[pc];
            int c11 = AT1[pr]*AT1[pc];
#pragma unroll
            for (int j = 0; j < 6; j++)
#pragma unroll
            for (int i = 0; i < 2; i++) {
                float v = mm[j][i];
                if (c00 ==  1) y[j][i][0] += v;
                if (c00 == -1) y[j][i][0] -= v;
                if (c01 ==  1) y[j][i][1] += v;
                if (c01 == -1) y[j][i][1] -= v;
                if (c10 ==  1) y[j][i][2] += v;
                if (c10 == -1) y[j][i][2] -= v;
                if (c11 ==  1) y[j][i][3] += v;
                if (c11 == -1) y[j][i][3] -= v;
            }
        }
    }

    int ty = lane2 >> 3, tx = lane2 & 7;
    int pooy = by*8 + ty, poox = bx*8 + tx;
#pragma unroll
    for (int j = 0; j < 6; j++) {
        int co = warp6 + j;
        float bco = __ldg(&bias[co]);
        float s = 0.f, qq = 0.f;
        float pooled[2];
#pragma unroll
        for (int i = 0; i < 2; i++) {
            float v0 = y[j][i][0] + bco;
            float v1 = y[j][i][1] + bco;
            float v2 = y[j][i][2] + bco;
            float v3 = y[j][i][3] + bco;
            s += (v0+v1) + (v2+v3);
            qq = fmaf(v0,v0, fmaf(v1,v1, fmaf(v2,v2, fmaf(v3,v3, qq))));
            pooled[i] = fmaxf(fmaxf(v0, v1), fmaxf(v2, v3));
        }
        float* dst = g_x2 + ((b*C2 + co)*H4 + pooy)*H4 + poox;
        *(float2*)dst = make_float2(pooled[0], pooled[1]);
        for (int o = 16; o > 0; o >>= 1) {
            s  += __shfl_down_sync(0xffffffffu, s,  o);
            qq += __shfl_down_sync(0xffffffffu, qq, o);
        }
        if (lane == 0) {
            atomicAdd(&g_s2[co*64], (double)s);
            atomicAdd(&g_q2[co*64], (double)qq);
        }
    }
}

// ---------------- feat GEMM split-K (R9 layout); bn2 finalize folded in -----
__global__ void __launch_bounds__(256) k_feat_part(const float* __restrict__ fw,
        const float* __restrict__ bn2g, const float* __restrict__ bn2b) {
    __shared__ float xs[NB*33];
    __shared__ float wsm[C2*33];
    __shared__ float bs2[C2], bh2[C2];
    if (threadIdx.x < C2) {
        int c = threadIdx.x;
        double m = g_s2[c*64] * INV_N2;
        double v = g_q2[c*64] * INV_N2 - m*m;
        float sc = bn2g[c] * rsqrtf((float)v + EPSV);
        bs2[c] = sc;
        bh2[c] = bn2b[c] - (float)m * sc;
    }
    int k0  = blockIdx.x * KCH;
    int tid = threadIdx.x;
    int bi  = tid & 15;
    int oi  = tid >> 4;
    int kl  = tid & 31;
    int rr  = tid >> 5;
    float acc[4][3];
#pragma unroll
    for (int i = 0; i < 4; i++)
#pragma unroll
    for (int j = 0; j < 3; j++) acc[i][j] = 0.f;

#pragma unroll 1
    for (int kk = 0; kk < KCH; kk += 32) {
        __syncthreads();
        int kidx = k0 + kk + kl;
        int ch   = kidx / (H4*H4);
        float sc = bs2[ch], sh = bh2[ch];
#pragma unroll
        for (int r = 0; r < 8; r++) {
            int bb = r*8 + rr;
            float raw = g_x2[bb*K2LEN + kidx];
            xs[bb*33 + kl] = fmaxf(fmaf(raw, sc, sh), 0.f);
        }
#pragma unroll
        for (int r = 0; r < 6; r++) {
            int oo = r*8 + rr;
            wsm[oo*33 + kl] = fw[(size_t)oo*K2LEN + kidx];
        }
        __syncthreads();
#pragma unroll
        for (int k = 0; k < 32; k++) {
            float xv[4], wv[3];
#pragma unroll
            for (int i = 0; i < 4; i++) xv[i] = xs[(bi*4 + i)*33 + k];
#pragma unroll
            for (int j = 0; j < 3; j++) wv[j] = wsm[(oi*3 + j)*33 + k];
#pragma unroll
            for (int i = 0; i < 4; i++)
#pragma unroll
            for (int j = 0; j < 3; j++)
                acc[i][j] = fmaf(xv[i], wv[j], acc[i][j]);
        }
    }
#pragma unroll
    for (int i = 0; i < 4; i++)
#pragma unroll
    for (int j = 0; j < 3; j++)
        g_part[(size_t)blockIdx.x*NB*C2 + (bi*4 + i)*C2 + (oi*3 + j)] = acc[i][j];
}

// ---------------- feat reduce + (last block, 12-block grid) MLP head --------
__global__ void k_feat_reduce(const float* __restrict__ fb,
                              const float* __restrict__ l1w, const float* __restrict__ l1b,
                              const float* __restrict__ l2w, const float* __restrict__ l2b,
                              float* __restrict__ out) {
    __shared__ bool isLast;
    int i = blockIdx.x*256 + threadIdx.x;
    if (i < NB*C2) {
        float s = 0.f;
#pragma unroll 4
        for (int n = 0; n < NCHUNK; n++) s += g_part[n*NB*C2 + i];
        g_feat[i] = s + fb[i % C2];
    }
    __syncthreads();
    if (threadIdx.x == 0) {
        __threadfence();
        isLast = (atomicAdd(&g_cnt3, 1u) == gridDim.x - 1u);
    }
    __syncthreads();
    if (isLast && threadIdx.x < NB) {
        int b = threadIdx.x;
        float f[48];
#pragma unroll
        for (int k = 0; k < 48; k++) f[k] = __ldcg(&g_feat[b*48 + k]);
        float h[24];
#pragma unroll 1
        for (int j = 0; j < 24; j++) {
            float s = l1b[j];
            for (int k = 0; k < 48; k++)
                s = fmaf(l1w[j*48 + k], f[k], s);
            h[j] = fmaxf(s, 0.f);
        }
        float t[4];
#pragma unroll
        for (int ii = 0; ii < 4; ii++) {
            float s = l2b[ii];
#pragma unroll
            for (int j = 0; j < 24; j++)
                s = fmaf(l2w[ii*24 + j], h[j], s);
            t[ii] = s;
        }
        float tx = t[0], tyv = t[1], sc = t[2], an = t[3];
        float cs = cosf(an), sn = sinf(an);
        g_theta[b*6 + 0] =  sc*cs;
        g_theta[b*6 + 1] = -sc*sn;
        g_theta[b*6 + 2] =  tx;
        g_theta[b*6 + 3] =  sc*sn;
        g_theta[b*6 + 4] =  sc*cs;
        g_theta[b*6 + 5] =  tyv;
        out[NB*HH*WW +         b] = tx;
        out[NB*HH*WW +  64 +   b] = tyv;
        out[NB*HH*WW + 128 +   b] = sc;
        out[NB*HH*WW + 192 +   b] = an;
    }
}

// ---------------- affine grid + bilinear sample -----------------------------
__device__ __forceinline__ float tapf(const float* __restrict__ xb,
                                      float xf, float yf, float wgt) {
    bool valid = (xf >= 0.f) & (xf < (float)WW) & (yf >= 0.f) & (yf < (float)HH);
    int xi = (int)fminf(fmaxf(xf, 0.f), (float)(WW-1));
    int yi = (int)fminf(fmaxf(yf, 0.f), (float)(HH-1));
    float v = __ldg(&xb[yi*WW + xi]);
    return valid ? v*wgt : 0.f;
}

__global__ void k_sample(const float* __restrict__ x, float* __restrict__ out) {
    int idx = blockIdx.x*256 + threadIdx.x;      // 64*224*224 exact
    int b   = idx / (HH*WW);
    int rem = idx - b*(HH*WW);
    int r   = rem / WW;
    int c   = rem - r*WW;
    float xsn = (2.f*c + 1.f)/(float)WW - 1.f;
    float ysn = (2.f*r + 1.f)/(float)HH - 1.f;
    const float* th = g_theta + b*6;
    float gx = th[0]*xsn + th[1]*ysn + th[2];
    float gy = th[3]*xsn + th[4]*ysn + th[5];
    float ix = ((gx + 1.f)*(float)WW - 1.f)*0.5f;
    float iy = ((gy + 1.f)*(float)HH - 1.f)*0.5f;
    float x0 = floorf(ix), y0 = floorf(iy);
    float x1 = x0 + 1.f,   y1 = y0 + 1.f;
    float wx1 = ix - x0, wx0 = 1.f - wx1;
    float wy1 = iy - y0, wy0 = 1.f - wy1;
    const float* xb = x + b*HH*WW;
    float o = tapf(xb, x0, y0, wx0*wy0)
            + tapf(xb, x1, y0, wx1*wy0)
            + tapf(xb, x0, y1, wx0*wy1)
            + tapf(xb, x1, y1, wx1*wy1);
    out[idx] = o;
}

// ---------------- launch ----------------------------------------------------
extern "C" void kernel_launch(void* const* d_in, const int* in_sizes, int n_in,
                              void* d_out, int out_size) {
    (void)in_sizes; (void)n_in; (void)out_size;
    const float* x    = (const float*)d_in[0];
    const float* c1w  = (const float*)d_in[1];
    const float* c1b  = (const float*)d_in[2];
    const float* bn1g = (const float*)d_in[3];
    const float* bn1b = (const float*)d_in[4];
    const float* c2w  = (const float*)d_in[5];
    const float* c2b  = (const float*)d_in[6];
    const float* bn2g = (const float*)d_in[7];
    const float* bn2b = (const float*)d_in[8];
    const float* fw   = (const float*)d_in[9];
    const float* fb   = (const float*)d_in[10];
    const float* l1w  = (const float*)d_in[11];
    const float* l1b  = (const float*)d_in[12];
    const float* l2w  = (const float*)d_in[13];
    const float* l2b  = (const float*)d_in[14];
    float* out = (float*)d_out;

    k_init<<<12, 256>>>(c2w);
    k_conv1<<<3136, 256>>>(x, c1w, c1b);
    k_conv2w<<<NB*49, 256>>>(c2b, bn1g, bn1b);
    k_feat_part<<<NCHUNK, 256>>>(fw, bn2g, bn2b);
    k_feat_reduce<<<12, 256>>>(fb, l1w, l1b, l2w, l2b, out);
    k_sample<<<(NB*HH*WW)/256, 256>>>(x, out);
}

// round 17
// speedup vs baseline: 1.3093x; 1.0012x over previous
#include <cuda_runtime.h>
#include <math.h>

#define NB 64
#define HH 224
#define WW 224
#define C1 24
#define C2 48
#define H2 112
#define H4 56
#define EPSV 1e-5f
#define K2LEN 150528   /* C2*H4*H4 */
#define KCH 256
#define NCHUNK 588     /* 588*256 = 150528 */

#define INV_N1 (1.0/((double)NB*HH*WW))
#define INV_N2 (1.0/((double)NB*H2*H2))

// conv2w dynamic smem layout (floats)
#define OFS_IS   0        /* 24ci x 18 rows x stride20 = 8640 */
#define OFS_VP   8640     /* 2 x 1536 */
#define OFS_US   11712    /* 2 x 1152 */
#define OFS_B1S  14016    /* 24 */
#define OFS_B1B  14040    /* 24 */
#define DYN_FLOATS 14064  /* 56256 bytes */

// ---------------- scratch (static __device__, no allocation) ----------------
__device__ float g_x1[NB*C1*H2*H2];          // RAW pooled conv1 output (pre-BN)
__device__ float g_x2[NB*C2*H4*H4];          // RAW pooled conv2 output (pre-BN)
__device__ float g_U[16*C1*C2];              // Winograd-transformed conv2 weights
__device__ double g_s1[C1*64];               // 512B stride -> distinct LTS slices
__device__ double g_q1[C1*64];
__device__ double g_s2[C2*64];
__device__ double g_q2[C2*64];
__device__ float g_part[NCHUNK*NB*C2];
__device__ float g_feat[NB*C2];
__device__ float g_theta[NB*6];
__device__ unsigned g_cnt3;                  // last-block counter (feat_reduce only)

// ---------------- init: zero accumulators/counter + Winograd U --------------
__global__ void k_init(const float* __restrict__ wt) {
    int i = blockIdx.x*256 + threadIdx.x;
    if (i < C1*64) { g_s1[i] = 0.0; g_q1[i] = 0.0; }
    if (i < C2*64) { g_s2[i] = 0.0; g_q2[i] = 0.0; }
    if (i == 0) g_cnt3 = 0u;
    if (i < C2*C1) {
        int co = i / C1, ci = i - co*C1;
        const float* g = wt + i*9;
        float T[4][3];
#pragma unroll
        for (int c = 0; c < 3; c++) {
            float g0 = g[0*3+c], g1 = g[1*3+c], g2 = g[2*3+c];
            T[0][c] = g0;
            T[1][c] = 0.5f*(g0 + g1 + g2);
            T[2][c] = 0.5f*(g0 - g1 + g2);
            T[3][c] = g2;
        }
#pragma unroll
        for (int pr = 0; pr < 4; pr++) {
            float t0 = T[pr][0], t1 = T[pr][1], t2 = T[pr][2];
            g_U[((pr*4+0)*C1 + ci)*C2 + co] = t0;
            g_U[((pr*4+1)*C1 + ci)*C2 + co] = 0.5f*(t0 + t1 + t2);
            g_U[((pr*4+2)*C1 + ci)*C2 + co] = 0.5f*(t0 - t1 + t2);
            g_U[((pr*4+3)*C1 + ci)*C2 + co] = t2;
        }
    }
}

// ---------------- conv1: conv + stats + raw maxpool -------------------------
__global__ void __launch_bounds__(256) k_conv1(const float* __restrict__ x,
        const float* __restrict__ w, const float* __restrict__ bias) {
    __shared__ float ws[C1*9];
    __shared__ float wb[C1];
    __shared__ float bacc[C1*2];
    for (int i = threadIdx.x; i < C1*9; i += 256) ws[i] = w[i];
    if (threadIdx.x < C1) wb[threadIdx.x] = bias[threadIdx.x];
    if (threadIdx.x < C1*2) bacc[threadIdx.x] = 0.f;
    __syncthreads();

    int idx = blockIdx.x*256 + threadIdx.x;   // 64*112*112 exact
    int b   = idx / (H2*H2);
    int rem = idx - b*(H2*H2);
    int py  = rem / H2;
    int px  = rem - py*H2;
    const float* xb = x + b*HH*WW;

    float tap[4][4];
#pragma unroll
    for (int r = 0; r < 4; r++) {
        int gy = 2*py - 1 + r;
        bool vy = (unsigned)gy < HH;
#pragma unroll
        for (int cc = 0; cc < 4; cc++) {
            int gx = 2*px - 1 + cc;
            tap[r][cc] = (vy && (unsigned)gx < WW) ? xb[gy*WW + gx] : 0.f;
        }
    }
    int lane = threadIdx.x & 31;
    float* o1 = g_x1 + b*C1*H2*H2 + py*H2 + px;
#pragma unroll
    for (int c = 0; c < C1; c++) {
        float v00 = wb[c], v01 = wb[c], v10 = wb[c], v11 = wb[c];
#pragma unroll
        for (int r = 0; r < 3; r++)
#pragma unroll
        for (int k = 0; k < 3; k++) {
            float wv = ws[c*9 + r*3 + k];
            v00 = fmaf(wv, tap[r  ][k  ], v00);
            v01 = fmaf(wv, tap[r  ][k+1], v01);
            v10 = fmaf(wv, tap[r+1][k  ], v10);
            v11 = fmaf(wv, tap[r+1][k+1], v11);
        }
        o1[c*H2*H2] = fmaxf(fmaxf(v00, v01), fmaxf(v10, v11));
        float s = (v00+v01) + (v10+v11);
        float q = fmaf(v00,v00, fmaf(v01,v01, fmaf(v10,v10, v11*v11)));
        for (int o = 16; o > 0; o >>= 1) {
            s += __shfl_down_sync(0xffffffffu, s, o);
            q += __shfl_down_sync(0xffffffffu, q, o);
        }
        if (lane == 0) {
            atomicAdd(&bacc[c],      s);
            atomicAdd(&bacc[C1 + c], q);
        }
    }
    __syncthreads();
    if (threadIdx.x < C1)
        atomicAdd(&g_s1[threadIdx.x*64], (double)bacc[threadIdx.x]);
    else if (threadIdx.x < C1*2)
        atomicAdd(&g_q1[(threadIdx.x-C1)*64], (double)bacc[threadIdx.x]);
}

// ---------------- cp.async helpers ------------------------------------------
__device__ __forceinline__ void cpa16(unsigned dst, const void* src) {
    asm volatile("cp.async.cg.shared.global [%0], [%1], 16;" :: "r"(dst), "l"(src));
}
__device__ __forceinline__ void cpU(float* UsBase, int p, int tid) {
    const float4* src = (const float4*)(g_U + p*C1*C2);   // 288 float4
    unsigned dst = (unsigned)__cvta_generic_to_shared(UsBase);
    cpa16(dst + tid*16u, src + tid);
    if (tid < 32) cpa16(dst + (256u+tid)*16u, src + 256 + tid);
    asm volatile("cp.async.commit_group;" ::: "memory");
}

// V-fill for one p (pr,pc compile-time when unrolled)
__device__ __forceinline__ void fillV(const float* Is, float* Vd, int pr, int pc, int tid) {
    const int   IA[4] = {0, 1, 1, 1};
    const int   IB[4] = {2, 2, 2, 3};
    const float SA[4] = {1.f, 1.f, -1.f, 1.f};
    const float SB[4] = {-1.f, 1.f, 1.f, -1.f};
    int ar0 = IA[pr]*20, ar1 = IB[pr]*20;
    int ac0 = IA[pc],    ac1 = IB[pc];
    float sr0 = SA[pr], sr1 = SB[pr];
    float c0 = SA[pc], c1 = SB[pc];
#pragma unroll
    for (int k = 0; k < 6; k++) {
        int v  = tid + k*256;
        int ci = v >> 6;
        int t  = v & 63;
        int ty = t >> 3, tx = t & 7;
        const float* dP = Is + ci*360 + (2*ty)*20 + 2*tx;
        float d00 = dP[ar0 + ac0], d01 = dP[ar0 + ac1];
        float d10 = dP[ar1 + ac0], d11 = dP[ar1 + ac1];
        Vd[v] = sr0*(c0*d00 + c1*d01) + sr1*(c0*d10 + c1*d11);
    }
}

// ---------------- conv2 Winograd F(2x2,3x3), dbl-buffered V+U, 1 sync/p -----
// dynamic smem 56.3KB; bn1 finalize recomputed per block (kernel-boundary
// ordering makes g_s1/g_q1 complete & deterministic).
__global__ void __launch_bounds__(256, 2) k_conv2w(const float* __restrict__ bias,
        const float* __restrict__ bn1g, const float* __restrict__ bn1b) {
    extern __shared__ __align__(16) float dyn[];
    float* Is   = dyn + OFS_IS;
    float* Vp   = dyn + OFS_VP;
    float* Us   = dyn + OFS_US;
    float* b1s_ = dyn + OFS_B1S;
    float* b1b_ = dyn + OFS_B1B;

    int tid = threadIdx.x;
    if (tid < C1) {
        int c = tid;
        double m = g_s1[c*64] * INV_N1;
        double v = g_q1[c*64] * INV_N1 - m*m;
        float sc = bn1g[c] * rsqrtf((float)v + EPSV);
        b1s_[c] = sc;
        b1b_[c] = bn1b[c] - (float)m * sc;
    }
    __syncthreads();

    int blk = blockIdx.x;                 // 64 * 49
    int b   = blk / 49;
    int rem = blk - b*49;
    int by  = rem / 7;
    int bx  = rem - by*7;
    int oy0 = by*16, ox0 = bx*16;

    const float* x1b = g_x1 + b*C1*H2*H2;
    for (int i = tid; i < C1*324; i += 256) {
        int ci = i / 324;
        int r2 = i - ci*324;
        int r  = r2 / 18;
        int c  = r2 - r*18;
        int gy = oy0 - 1 + r;
        int gx = ox0 - 1 + c;
        float v = ((unsigned)gy < H2 && (unsigned)gx < H2) ? x1b[(ci*H2 + gy)*H2 + gx] : 0.f;
        Is[ci*360 + r*20 + c] = fmaxf(fmaf(v, b1s_[ci], b1b_[ci]), 0.f);
    }

    int lane  = tid & 31;
    int warp  = tid >> 5;
    int warp6 = warp*6;
    int lane2 = lane*2;

    float y[6][2][4];
#pragma unroll
    for (int j = 0; j < 6; j++)
#pragma unroll
    for (int i = 0; i < 2; i++) {
        y[j][i][0] = 0.f; y[j][i][1] = 0.f; y[j][i][2] = 0.f; y[j][i][3] = 0.f;
    }

    const int AT0[4] = {1, 1, 1, 0};
    const int AT1[4] = {0, 1, -1, -1};

    __syncthreads();                      // Is ready
    // prologue: V(0) + U(0)
    fillV(Is, Vp, 0, 0, tid);
    cpU(Us, 0, tid);
    asm volatile("cp.async.wait_group 0;" ::: "memory");
    __syncthreads();

#pragma unroll
    for (int p = 0; p < 16; p++) {
        // prefetch next p's operands into alternate buffers (overlaps GEMM)
        if (p < 15) {
            cpU(Us + ((p+1)&1)*1152, p+1, tid);
            fillV(Is, Vp + ((p+1)&1)*1536, (p+1)>>2, (p+1)&3, tid);
        }
        // GEMM(p) entirely from smem
        const float* Vs = Vp + (p&1)*1536;
        const float* Up = Us + (p&1)*1152 + warp6;
        float m00=0.f, m01=0.f, m10=0.f, m11=0.f, m20=0.f, m21=0.f;
        float m30=0.f, m31=0.f, m40=0.f, m41=0.f, m50=0.f, m51=0.f;
#pragma unroll 6
        for (int ci = 0; ci < C1; ci++) {
            float2 vv = *(const float2*)&Vs[ci*64 + lane2];
            const float* up = Up + ci*C2;
            float2 u0 = *(const float2*)(up);
            float2 u1 = *(const float2*)(up + 2);
            float2 u2 = *(const float2*)(up + 4);
            m00 = fmaf(u0.x, vv.x, m00); m01 = fmaf(u0.x, vv.y, m01);
            m10 = fmaf(u0.y, vv.x, m10); m11 = fmaf(u0.y, vv.y, m11);
            m20 = fmaf(u1.x, vv.x, m20); m21 = fmaf(u1.x, vv.y, m21);
            m30 = fmaf(u1.y, vv.x, m30); m31 = fmaf(u1.y, vv.y, m31);
            m40 = fmaf(u2.x, vv.x, m40); m41 = fmaf(u2.x, vv.y, m41);
            m50 = fmaf(u2.y, vv.x, m50); m51 = fmaf(u2.y, vv.y, m51);
        }
        float mm[6][2] = {{m00,m01},{m10,m11},{m20,m21},{m30,m31},{m40,m41},{m50,m51}};
        int pr = p >> 2, pc = p & 3;
        int c00 = AT0[pr]*AT0[pc];
        int c01 = AT0[pr]*AT1[pc];
        int c10 = AT1[pr]*AT0[pc];
        int c11 = AT1[pr]*AT1[pc];
#pragma unroll
        for (int j = 0; j < 6; j++)
#pragma unroll
        for (int i = 0; i < 2; i++) {
            float v = mm[j][i];
            if (c00 ==  1) y[j][i][0] += v;
            if (c00 == -1) y[j][i][0] -= v;
            if (c01 ==  1) y[j][i][1] += v;
            if (c01 == -1) y[j][i][1] -= v;
            if (c10 ==  1) y[j][i][2] += v;
            if (c10 == -1) y[j][i][2] -= v;
            if (c11 ==  1) y[j][i][3] += v;
            if (c11 == -1) y[j][i][3] -= v;
        }
        if (p < 15) {
            asm volatile("cp.async.wait_group 0;" ::: "memory");
            __syncthreads();          // next-p buffers visible; 1 barrier per p
        }
    }

    // ---- epilogue: bias, stats, pool (tile == pool window), store ----------
    int ty = lane2 >> 3, tx = lane2 & 7;
    int pooy = by*8 + ty, poox = bx*8 + tx;
#pragma unroll
    for (int j = 0; j < 6; j++) {
        int co = warp6 + j;
        float bco = __ldg(&bias[co]);
        float s = 0.f, qq = 0.f;
        float pooled[2];
#pragma unroll
        for (int i = 0; i < 2; i++) {
            float v0 = y[j][i][0] + bco;
            float v1 = y[j][i][1] + bco;
            float v2 = y[j][i][2] + bco;
            float v3 = y[j][i][3] + bco;
            s += (v0+v1) + (v2+v3);
            qq = fmaf(v0,v0, fmaf(v1,v1, fmaf(v2,v2, fmaf(v3,v3, qq))));
            pooled[i] = fmaxf(fmaxf(v0, v1), fmaxf(v2, v3));
        }
        float* dst = g_x2 + ((b*C2 + co)*H4 + pooy)*H4 + poox;
        *(float2*)dst = make_float2(pooled[0], pooled[1]);
        for (int o = 16; o > 0; o >>= 1) {
            s  += __shfl_down_sync(0xffffffffu, s,  o);
            qq += __shfl_down_sync(0xffffffffu, qq, o);
        }
        if (lane == 0) {
            atomicAdd(&g_s2[co*64], (double)s);
            atomicAdd(&g_q2[co*64], (double)qq);
        }
    }
}

// ---------------- feat GEMM split-K (R9 layout); bn2 finalize folded in -----
__global__ void __launch_bounds__(256) k_feat_part(const float* __restrict__ fw,
        const float* __restrict__ bn2g, const float* __restrict__ bn2b) {
    __shared__ float xs[NB*33];
    __shared__ float wsm[C2*33];
    __shared__ float bs2[C2], bh2[C2];
    if (threadIdx.x < C2) {
        int c = threadIdx.x;
        double m = g_s2[c*64] * INV_N2;
        double v = g_q2[c*64] * INV_N2 - m*m;
        float sc = bn2g[c] * rsqrtf((float)v + EPSV);
        bs2[c] = sc;
        bh2[c] = bn2b[c] - (float)m * sc;
    }
    int k0  = blockIdx.x * KCH;
    int tid = threadIdx.x;
    int bi  = tid & 15;
    int oi  = tid >> 4;
    int kl  = tid & 31;
    int rr  = tid >> 5;
    float acc[4][3];
#pragma unroll
    for (int i = 0; i < 4; i++)
#pragma unroll
    for (int j = 0; j < 3; j++) acc[i][j] = 0.f;

#pragma unroll 1
    for (int kk = 0; kk < KCH; kk += 32) {
        __syncthreads();
        int kidx = k0 + kk + kl;
        int ch   = kidx / (H4*H4);
        float sc = bs2[ch], sh = bh2[ch];
#pragma unroll
        for (int r = 0; r < 8; r++) {
            int bb = r*8 + rr;
            float raw = g_x2[bb*K2LEN + kidx];
            xs[bb*33 + kl] = fmaxf(fmaf(raw, sc, sh), 0.f);
        }
#pragma unroll
        for (int r = 0; r < 6; r++) {
            int oo = r*8 + rr;
            wsm[oo*33 + kl] = fw[(size_t)oo*K2LEN + kidx];
        }
        __syncthreads();
#pragma unroll
        for (int k = 0; k < 32; k++) {
            float xv[4], wv[3];
#pragma unroll
            for (int i = 0; i < 4; i++) xv[i] = xs[(bi*4 + i)*33 + k];
#pragma unroll
            for (int j = 0; j < 3; j++) wv[j] = wsm[(oi*3 + j)*33 + k];
#pragma unroll
            for (int i = 0; i < 4; i++)
#pragma unroll
            for (int j = 0; j < 3; j++)
                acc[i][j] = fmaf(xv[i], wv[j], acc[i][j]);
        }
    }
#pragma unroll
    for (int i = 0; i < 4; i++)
#pragma unroll
    for (int j = 0; j < 3; j++)
        g_part[(size_t)blockIdx.x*NB*C2 + (bi*4 + i)*C2 + (oi*3 + j)] = acc[i][j];
}

// ---------------- feat reduce + (last block, 12-block grid) MLP head --------
__global__ void k_feat_reduce(const float* __restrict__ fb,
                              const float* __restrict__ l1w, const float* __restrict__ l1b,
                              const float* __restrict__ l2w, const float* __restrict__ l2b,
                              float* __restrict__ out) {
    __shared__ bool isLast;
    int i = blockIdx.x*256 + threadIdx.x;
    if (i < NB*C2) {
        float s = 0.f;
#pragma unroll 4
        for (int n = 0; n < NCHUNK; n++) s += g_part[n*NB*C2 + i];
        g_feat[i] = s + fb[i % C2];
    }
    __syncthreads();
    if (threadIdx.x == 0) {
        __threadfence();
        isLast = (atomicAdd(&g_cnt3, 1u) == gridDim.x - 1u);
    }
    __syncthreads();
    if (isLast && threadIdx.x < NB) {
        int b = threadIdx.x;
        float f[48];
#pragma unroll
        for (int k = 0; k < 48; k++) f[k] = __ldcg(&g_feat[b*48 + k]);
        float h[24];
#pragma unroll 1
        for (int j = 0; j < 24; j++) {
            float s = l1b[j];
            for (int k = 0; k < 48; k++)
                s = fmaf(l1w[j*48 + k], f[k], s);
            h[j] = fmaxf(s, 0.f);
        }
        float t[4];
#pragma unroll
        for (int ii = 0; ii < 4; ii++) {
            float s = l2b[ii];
#pragma unroll
            for (int j = 0; j < 24; j++)
                s = fmaf(l2w[ii*24 + j], h[j], s);
            t[ii] = s;
        }
        float tx = t[0], tyv = t[1], sc = t[2], an = t[3];
        float cs = cosf(an), sn = sinf(an);
        g_theta[b*6 + 0] =  sc*cs;
        g_theta[b*6 + 1] = -sc*sn;
        g_theta[b*6 + 2] =  tx;
        g_theta[b*6 + 3] =  sc*sn;
        g_theta[b*6 + 4] =  sc*cs;
        g_theta[b*6 + 5] =  tyv;
        out[NB*HH*WW +         b] = tx;
        out[NB*HH*WW +  64 +   b] = tyv;
        out[NB*HH*WW + 128 +   b] = sc;
        out[NB*HH*WW + 192 +   b] = an;
    }
}

// ---------------- affine grid + bilinear sample -----------------------------
__device__ __forceinline__ float tapf(const float* __restrict__ xb,
                                      float xf, float yf, float wgt) {
    bool valid = (xf >= 0.f) & (xf < (float)WW) & (yf >= 0.f) & (yf < (float)HH);
    int xi = (int)fminf(fmaxf(xf, 0.f), (float)(WW-1));
    int yi = (int)fminf(fmaxf(yf, 0.f), (float)(HH-1));
    float v = __ldg(&xb[yi*WW + xi]);
    return valid ? v*wgt : 0.f;
}

__global__ void k_sample(const float* __restrict__ x, float* __restrict__ out) {
    int idx = blockIdx.x*256 + threadIdx.x;      // 64*224*224 exact
    int b   = idx / (HH*WW);
    int rem = idx - b*(HH*WW);
    int r   = rem / WW;
    int c   = rem - r*WW;
    float xsn = (2.f*c + 1.f)/(float)WW - 1.f;
    float ysn = (2.f*r + 1.f)/(float)HH - 1.f;
    const float* th = g_theta + b*6;
    float gx = th[0]*xsn + th[1]*ysn + th[2];
    float gy = th[3]*xsn + th[4]*ysn + th[5];
    float ix = ((gx + 1.f)*(float)WW - 1.f)*0.5f;
    float iy = ((gy + 1.f)*(float)HH - 1.f)*0.5f;
    float x0 = floorf(ix), y0 = floorf(iy);
    float x1 = x0 + 1.f,   y1 = y0 + 1.f;
    float wx1 = ix - x0, wx0 = 1.f - wx1;
    float wy1 = iy - y0, wy0 = 1.f - wy1;
    const float* xb = x + b*HH*WW;
    float o = tapf(xb, x0, y0, wx0*wy0)
            + tapf(xb, x1, y0, wx1*wy0)
            + tapf(xb, x0, y1, wx0*wy1)
            + tapf(xb, x1, y1, wx1*wy1);
    out[idx] = o;
}

// ---------------- launch ----------------------------------------------------
extern "C" void kernel_launch(void* const* d_in, const int* in_sizes, int n_in,
                              void* d_out, int out_size) {
    (void)in_sizes; (void)n_in; (void)out_size;
    const float* x    = (const float*)d_in[0];
    const float* c1w  = (const float*)d_in[1];
    const float* c1b  = (const float*)d_in[2];
    const float* bn1g = (const float*)d_in[3];
    const float* bn1b = (const float*)d_in[4];
    const float* c2w  = (const float*)d_in[5];
    const float* c2b  = (const float*)d_in[6];
    const float* bn2g = (const float*)d_in[7];
    const float* bn2b = (const float*)d_in[8];
    const float* fw   = (const float*)d_in[9];
    const float* fb   = (const float*)d_in[10];
    const float* l1w  = (const float*)d_in[11];
    const float* l1b  = (const float*)d_in[12];
    const float* l2w  = (const float*)d_in[13];
    const float* l2b  = (const float*)d_in[14];
    float* out = (float*)d_out;

    // opt-in >48KB dynamic smem for conv2w (attribute set; not an allocation)
    cudaFuncSetAttribute(k_conv2w, cudaFuncAttributeMaxDynamicSharedMemorySize,
                         DYN_FLOATS*4);

    k_init<<<12, 256>>>(c2w);
    k_conv1<<<3136, 256>>>(x, c1w, c1b);
    k_conv2w<<<NB*49, 256, DYN_FLOATS*4>>>(c2b, bn1g, bn1b);
    k_feat_part<<<NCHUNK, 256>>>(fw, bn2g, bn2b);
    k_feat_reduce<<<12, 256>>>(fb, l1w, l1b, l2w, l2b, out);
    k_sample<<<(NB*HH*WW)/256, 256>>>(x, out);
}